// round 4
// baseline (speedup 1.0000x reference)
#include <cuda_runtime.h>
#include <math.h>

#define BATCH 8
#define DD 24
#define HH 64
#define WW 128
#define HW (HH*WW)

typedef unsigned long long u64;

// ---------------- packed fp32x2 helpers (Blackwell dual-FP32 pipe) ----------------
__device__ __forceinline__ u64 pk(float lo, float hi) {
    u64 r; asm("mov.b64 %0, {%1,%2};" : "=l"(r) : "f"(lo), "f"(hi)); return r;
}
__device__ __forceinline__ u64 pk1(float v) { return pk(v, v); }
__device__ __forceinline__ void fma2(u64& d, u64 a, u64 b) {
    asm("fma.rn.f32x2 %0, %1, %2, %0;" : "+l"(d) : "l"(a), "l"(b));
}
__device__ __forceinline__ float2 unpk(u64 v) {
    float2 f; asm("mov.b64 {%0,%1}, %2;" : "=f"(f.x), "=f"(f.y) : "l"(v)); return f;
}

// ---------------- scratch (device globals; no allocations allowed) ----------------
__device__ float g_cv[BATCH*8*DD*HH*WW];        // cost volume (B,8,24,64,128)
__device__ float g_x1[BATCH*16*DD*HH*WW];       // conv1 raw
__device__ float g_x1n[BATCH*16*DD*HH*WW];      // conv1 GN+silu
__device__ float g_x2[BATCH*16*DD*HH*WW];       // conv2 raw
__device__ float g_x2n[BATCH*16*DD*HH*WW];      // conv2 GN+silu
__device__ float g_logits[BATCH*DD*HH*WW];      // conv3 output
__device__ float g_feat[BATCH*16*HH*WW];        // feat conv raw
__device__ double g_stats[3*BATCH*8*2];         // [layer][b][group][{sum,sumsq}]

// ---------------- zero stats ----------------
__global__ void k_zero_stats() {
    int i = threadIdx.x;
    if (i < 3*BATCH*8*2) g_stats[i] = 0.0;
}

// ---------------- cost volume ----------------
__global__ void __launch_bounds__(128) k_costvol(const float* __restrict__ fL,
                                                 const float* __restrict__ fR) {
    __shared__ float sR[16*128];
    int x = blockIdx.x;
    int h = x & 63;
    int g = (x >> 6) & 7;
    int b = x >> 9;
    int tid = threadIdx.x;

    const float* baseL = fL + (((size_t)(b*128 + g*16))*HH + h)*WW;
    const float* baseR = fR + (((size_t)(b*128 + g*16))*HH + h)*WW;
    float l[16];
#pragma unroll
    for (int c = 0; c < 16; c++) {
        l[c] = baseL[(size_t)c*HW + tid];
        sR[c*128 + tid] = baseR[(size_t)c*HW + tid];
    }
    __syncthreads();

    float* ov = g_cv + (((size_t)(b*8 + g)*DD)*HH + h)*WW + tid;
    for (int d = 0; d < DD; d++) {
        float s = 0.f;
        if (tid >= d) {
#pragma unroll
            for (int c = 0; c < 16; c++) s += l[c] * sR[c*128 + tid - d];
            s *= 0.0625f;
        }
        ov[(size_t)d*HW] = s;
    }
}

// ---------------- conv3d, 16 oc, fused GN stats, FMA2 (w-pair acc, u64 weights) ----
// grid = B*24*16, block = 128; thread: 8 oc x 8 w (4 w-pairs)
template<int LAYER>
__global__ void __launch_bounds__(128, 3) k_conv3d16(const float* __restrict__ wts) {
    constexpr int CIN = (LAYER == 0) ? 8 : 16;
    constexpr int NPASS = CIN / 8;
    const float* in = (LAYER == 0) ? g_cv : g_x1n;
    float* out = (LAYER == 0) ? g_x1 : g_x2;
    double* stats = g_stats + LAYER*128;

    __shared__ __align__(16) u64 swt[8*27*16];   // duplicated weight pairs, [icl][tap][oc]
    __shared__ float sred[16];
    int tid = threadIdx.x;
    if (tid < 16) sred[tid] = 0.f;

    int x = blockIdx.x;
    int ht = x & 15;
    int d = (x >> 4) % 24;
    int b = x / 384;

    int wt = tid & 15, hr = (tid >> 4) & 3, os = tid >> 6;
    int w0 = wt << 3, h = (ht << 2) + hr, oc0 = os << 3;

    u64 acc[8][4];   // [oc][w-pair]
#pragma unroll
    for (int o = 0; o < 8; o++)
#pragma unroll
        for (int t = 0; t < 4; t++) acc[o][t] = 0ull;

    const float* inb = in + (size_t)b*CIN*DD*HW;

    for (int p = 0; p < NPASS; p++) {
        __syncthreads();
        for (int i = tid; i < 8*27*16; i += 128) {
            int icl = i / 432; int r = i - icl*432; int tap = r >> 4; int oc = r & 15;
            swt[i] = pk1(wts[(oc*CIN + p*8 + icl)*27 + tap]);
        }
        __syncthreads();

        for (int icl = 0; icl < 8; icl++) {
            const float* inc = inb + (size_t)(p*8 + icl)*DD*HW;
#pragma unroll
            for (int kd = 0; kd < 3; kd++) {
                int zd = d + kd - 1;
                if ((unsigned)zd >= (unsigned)DD) continue;
#pragma unroll
                for (int kh = 0; kh < 3; kh++) {
                    int zh = h + kh - 1;
                    if ((unsigned)zh >= (unsigned)HH) continue;
                    const float* row = inc + ((size_t)zd*HH + zh)*WW + w0;
                    float r0 = (w0 == 0) ? 0.f : __ldg(row - 1);
                    float4 va = *(const float4*)row;
                    float4 vb = *(const float4*)(row + 4);
                    float r9 = (w0 == 120) ? 0.f : __ldg(row + 8);
                    // input pairs: pe[t] = (r[2t], r[2t+1]), po[t] = (r[2t+1], r[2t+2])
                    u64 pe[5], po[4];
                    pe[0] = pk(r0, va.x);
                    pe[1] = pk(va.y, va.z);
                    pe[2] = pk(va.w, vb.x);
                    pe[3] = pk(vb.y, vb.z);
                    pe[4] = pk(vb.w, r9);
                    po[0] = pk(va.x, va.y);
                    po[1] = pk(va.z, va.w);
                    po[2] = pk(vb.x, vb.y);
                    po[3] = pk(vb.z, vb.w);
                    int tb = (kd*3 + kh)*3;
                    const u64* wbase = swt + (icl*27 + tb)*16 + oc0;
                    // kw = 0 : pairs pe[0..3] shifted by -1 => uses pe[t] (r[2t], r[2t+1]) with w[kw=0] maps out[2t]+... 
#pragma unroll
                    for (int o = 0; o < 8; o++) {
                        u64 wv0 = wbase[o];
                        fma2(acc[o][0], wv0, pe[0]);
                        fma2(acc[o][1], wv0, pe[1]);
                        fma2(acc[o][2], wv0, pe[2]);
                        fma2(acc[o][3], wv0, pe[3]);
                    }
#pragma unroll
                    for (int o = 0; o < 8; o++) {
                        u64 wv1 = wbase[16 + o];
                        fma2(acc[o][0], wv1, po[0]);
                        fma2(acc[o][1], wv1, po[1]);
                        fma2(acc[o][2], wv1, po[2]);
                        fma2(acc[o][3], wv1, po[3]);
                    }
#pragma unroll
                    for (int o = 0; o < 8; o++) {
                        u64 wv2 = wbase[32 + o];
                        fma2(acc[o][0], wv2, pe[1]);
                        fma2(acc[o][1], wv2, pe[2]);
                        fma2(acc[o][2], wv2, pe[3]);
                        fma2(acc[o][3], wv2, pe[4]);
                    }
                }
            }
        }
    }

    // store + per-group partial stats
    float gs[4], gs2[4];
#pragma unroll
    for (int i = 0; i < 4; i++) { gs[i] = 0.f; gs2[i] = 0.f; }
#pragma unroll
    for (int o = 0; o < 8; o++) {
        float v[8];
#pragma unroll
        for (int t = 0; t < 4; t++) { float2 f = unpk(acc[o][t]); v[2*t] = f.x; v[2*t+1] = f.y; }
        int oc = oc0 + o;
        float* orow = out + ((((size_t)b*16 + oc)*DD + d)*HH + h)*WW + w0;
        *(float4*)orow       = make_float4(v[0], v[1], v[2], v[3]);
        *(float4*)(orow + 4) = make_float4(v[4], v[5], v[6], v[7]);
        float s = 0.f, s2 = 0.f;
#pragma unroll
        for (int j = 0; j < 8; j++) { s += v[j]; s2 += v[j]*v[j]; }
        gs[o >> 1] += s; gs2[o >> 1] += s2;
    }
#pragma unroll
    for (int i = 0; i < 4; i++) {
        int grp = os*4 + i;
        atomicAdd(&sred[grp*2],     gs[i]);
        atomicAdd(&sred[grp*2 + 1], gs2[i]);
    }
    __syncthreads();
    if (tid < 16) atomicAdd(&stats[b*16 + tid], (double)sred[tid]);
}

// ---------------- GN finalize + apply + SiLU ----------------
__global__ void __launch_bounds__(256) k_norm(int which, float* outext,
                                              const float* __restrict__ gw,
                                              const float* __restrict__ gb,
                                              int nslab, float invN) {
    const float* in = (which == 0) ? g_x1 : (which == 1) ? g_x2 : g_feat;
    float* out = (which == 2) ? outext : ((which == 0) ? g_x1n : g_x2n);
    const double* st = g_stats + which*128;

    __shared__ float sA, sB;
    int x = blockIdx.x;
    int s = x % nslab;
    int c = (x / nslab) & 15;
    int b = x / (nslab*16);
    if (threadIdx.x == 0) {
        const double* p = st + ((size_t)b*8 + (c >> 1))*2;
        double mu = p[0] * (double)invN;
        double var = p[1] * (double)invN - mu*mu;
        float rstd = rsqrtf((float)var + 1e-5f);
        float A = rstd * gw[c];
        sA = A;
        sB = gb[c] - (float)mu * A;
    }
    __syncthreads();
    float A = sA, Bv = sB;

    size_t base = ((size_t)(b*16 + c)*nslab + s)*8192;
    const float4* ip = (const float4*)(in + base);
    float4* op = (float4*)(out + base);
    for (int i = threadIdx.x; i < 2048; i += 256) {
        float4 v = ip[i];
        v.x = v.x*A + Bv; v.y = v.y*A + Bv; v.z = v.z*A + Bv; v.w = v.w*A + Bv;
        v.x = v.x / (1.f + __expf(-v.x));
        v.y = v.y / (1.f + __expf(-v.y));
        v.z = v.z / (1.f + __expf(-v.z));
        v.w = v.w / (1.f + __expf(-v.w));
        op[i] = v;
    }
}

// ---------------- conv3d, 1 output channel (logits), FMA2 over w-pairs ----------------
__global__ void __launch_bounds__(128) k_conv3d_oc1(const float* __restrict__ wts,
                                                    const float* __restrict__ bias) {
    __shared__ u64 swt[432];
    int tid = threadIdx.x;
    for (int i = tid; i < 432; i += 128) swt[i] = pk1(wts[i]);
    __syncthreads();

    int x = blockIdx.x;
    int ht = x & 7;
    int d = (x >> 3) % 24;
    int b = x / 192;
    int wt = tid & 15, hr = tid >> 4;
    int w0 = wt << 3, h = ht*8 + hr;

    u64 acc[4];
#pragma unroll
    for (int t = 0; t < 4; t++) acc[t] = 0ull;

    const float* inb = g_x2n + (size_t)b*16*DD*HW;
    for (int ic = 0; ic < 16; ic++) {
        const float* inc = inb + (size_t)ic*DD*HW;
#pragma unroll
        for (int kd = 0; kd < 3; kd++) {
            int zd = d + kd - 1;
            if ((unsigned)zd >= (unsigned)DD) continue;
#pragma unroll
            for (int kh = 0; kh < 3; kh++) {
                int zh = h + kh - 1;
                if ((unsigned)zh >= (unsigned)HH) continue;
                const float* row = inc + ((size_t)zd*HH + zh)*WW + w0;
                float r0 = (w0 == 0) ? 0.f : __ldg(row - 1);
                float4 va = *(const float4*)row;
                float4 vb = *(const float4*)(row + 4);
                float r9 = (w0 == 120) ? 0.f : __ldg(row + 8);
                u64 pe[5], po[4];
                pe[0] = pk(r0, va.x);  pe[1] = pk(va.y, va.z);
                pe[2] = pk(va.w, vb.x); pe[3] = pk(vb.y, vb.z);
                pe[4] = pk(vb.w, r9);
                po[0] = pk(va.x, va.y); po[1] = pk(va.z, va.w);
                po[2] = pk(vb.x, vb.y); po[3] = pk(vb.z, vb.w);
                int tb = (kd*3 + kh)*3;
                u64 wv0 = swt[ic*27 + tb + 0];
                u64 wv1 = swt[ic*27 + tb + 1];
                u64 wv2 = swt[ic*27 + tb + 2];
#pragma unroll
                for (int t = 0; t < 4; t++) {
                    fma2(acc[t], wv0, pe[t]);
                    fma2(acc[t], wv1, po[t]);
                    fma2(acc[t], wv2, pe[t + 1]);
                }
            }
        }
    }
    float bs = bias[0];
    float o[8];
#pragma unroll
    for (int t = 0; t < 4; t++) { float2 f = unpk(acc[t]); o[2*t] = f.x + bs; o[2*t+1] = f.y + bs; }
    float* orow = g_logits + (((size_t)b*DD + d)*HH + h)*WW + w0;
    *(float4*)orow       = make_float4(o[0], o[1], o[2], o[3]);
    *(float4*)(orow + 4) = make_float4(o[4], o[5], o[6], o[7]);
}

// ---------------- softmax over D -> d_out, conf; zero sx, sy ----------------
__global__ void __launch_bounds__(128) k_softmax(float* __restrict__ out) {
    int x = blockIdx.x;
    int h = x & 63;
    int b = x >> 6;
    int w = threadIdx.x;
    const float* lp = g_logits + ((size_t)b*DD*HH + h)*WW + w;
    float l[DD];
    float m = -1e30f;
#pragma unroll
    for (int d = 0; d < DD; d++) { l[d] = lp[(size_t)d*HW]; m = fmaxf(m, l[d]); }
    float S = 0.f, E = 0.f;
#pragma unroll
    for (int d = 0; d < DD; d++) {
        float e = __expf(l[d] - m);
        S += e; E += e * (float)d;
    }
    float inv = 1.f / S;
    int oi = (b*HH + h)*WW + w;
    out[oi]           = E * inv;   // d_out
    out[65536 + oi]   = 0.f;       // sx
    out[131072 + oi]  = 0.f;       // sy
    out[1245184 + oi] = inv;       // conf
}

// ---------------- feature head conv2d (128->16 ch, 3x3) + GN stats, FMA2 ----------------
// grid = B*16*2, block = 128; thread: 4 oc x 8 w (4 w-pairs); weights staged in 4 passes
__global__ void __launch_bounds__(128, 3) k_conv2d_feat(const float* __restrict__ fL,
                                                        const float* __restrict__ wts) {
    __shared__ __align__(16) u64 swt[32*9*16];   // duplicated pairs for 32 input ch
    __shared__ float sred[16];
    int tid = threadIdx.x;
    if (tid < 16) sred[tid] = 0.f;

    int x = blockIdx.x;
    int wtile = x & 1;
    int ht = (x >> 1) & 15;
    int b = x >> 5;

    int wt = tid & 7, os = (tid >> 3) & 3, hr = tid >> 5;
    int w0 = wtile*64 + wt*8;
    int h = ht*4 + hr;
    int oc0 = os*4;

    u64 acc[4][4];   // [oc][w-pair]
#pragma unroll
    for (int o = 0; o < 4; o++)
#pragma unroll
        for (int t = 0; t < 4; t++) acc[o][t] = 0ull;

    for (int p = 0; p < 4; p++) {
        __syncthreads();
        for (int i = tid; i < 32*144; i += 128) {
            int icl = i / 144; int r = i - icl*144; int tap = r >> 4; int oc = r & 15;
            swt[i] = pk1(wts[((size_t)oc*128 + p*32 + icl)*9 + tap]);
        }
        __syncthreads();
        for (int icl = 0; icl < 32; icl++) {
            int ic = p*32 + icl;
            const float* rowb = fL + ((size_t)(b*128 + ic)*HH)*WW;
#pragma unroll
            for (int kh = 0; kh < 3; kh++) {
                int zh = h + kh - 1;
                if ((unsigned)zh >= (unsigned)HH) continue;
                const float* row = rowb + (size_t)zh*WW + w0;
                float r0 = (w0 == 0) ? 0.f : __ldg(row - 1);
                float4 va = *(const float4*)row;
                float4 vb = *(const float4*)(row + 4);
                float r9 = (w0 == 120) ? 0.f : __ldg(row + 8);
                u64 pe[5], po[4];
                pe[0] = pk(r0, va.x);  pe[1] = pk(va.y, va.z);
                pe[2] = pk(va.w, vb.x); pe[3] = pk(vb.y, vb.z);
                pe[4] = pk(vb.w, r9);
                po[0] = pk(va.x, va.y); po[1] = pk(va.z, va.w);
                po[2] = pk(vb.x, vb.y); po[3] = pk(vb.z, vb.w);
                const u64* wbase = swt + (icl*9 + kh*3)*16 + oc0;
#pragma unroll
                for (int o = 0; o < 4; o++) {
                    u64 wv0 = wbase[o];
                    fma2(acc[o][0], wv0, pe[0]);
                    fma2(acc[o][1], wv0, pe[1]);
                    fma2(acc[o][2], wv0, pe[2]);
                    fma2(acc[o][3], wv0, pe[3]);
                }
#pragma unroll
                for (int o = 0; o < 4; o++) {
                    u64 wv1 = wbase[16 + o];
                    fma2(acc[o][0], wv1, po[0]);
                    fma2(acc[o][1], wv1, po[1]);
                    fma2(acc[o][2], wv1, po[2]);
                    fma2(acc[o][3], wv1, po[3]);
                }
#pragma unroll
                for (int o = 0; o < 4; o++) {
                    u64 wv2 = wbase[32 + o];
                    fma2(acc[o][0], wv2, pe[1]);
                    fma2(acc[o][1], wv2, pe[2]);
                    fma2(acc[o][2], wv2, pe[3]);
                    fma2(acc[o][3], wv2, pe[4]);
                }
            }
        }
    }

    // store + stats (layer 2)
    float gs[2], gs2[2];
    gs[0] = gs[1] = gs2[0] = gs2[1] = 0.f;
#pragma unroll
    for (int o = 0; o < 4; o++) {
        float v[8];
#pragma unroll
        for (int t = 0; t < 4; t++) { float2 f = unpk(acc[o][t]); v[2*t] = f.x; v[2*t+1] = f.y; }
        int oc = oc0 + o;
        float* orow = g_feat + (((size_t)b*16 + oc)*HH + h)*WW + w0;
        *(float4*)orow       = make_float4(v[0], v[1], v[2], v[3]);
        *(float4*)(orow + 4) = make_float4(v[4], v[5], v[6], v[7]);
        float s = 0.f, s2 = 0.f;
#pragma unroll
        for (int j = 0; j < 8; j++) { s += v[j]; s2 += v[j]*v[j]; }
        gs[o >> 1] += s; gs2[o >> 1] += s2;
    }
#pragma unroll
    for (int i = 0; i < 2; i++) {
        int grp = os*2 + i;
        atomicAdd(&sred[grp*2],     gs[i]);
        atomicAdd(&sred[grp*2 + 1], gs2[i]);
    }
    __syncthreads();
    if (tid < 16) atomicAdd(&g_stats[2*128 + b*16 + tid], (double)sred[tid]);
}

// ---------------- launch ----------------
extern "C" void kernel_launch(void* const* d_in, const int* in_sizes, int n_in,
                              void* d_out, int out_size) {
    const float* fL    = (const float*)d_in[0];
    const float* fR    = (const float*)d_in[1];
    const float* w1    = (const float*)d_in[2];
    const float* gn1w  = (const float*)d_in[3];
    const float* gn1b  = (const float*)d_in[4];
    const float* w2    = (const float*)d_in[5];
    const float* gn2w  = (const float*)d_in[6];
    const float* gn2b  = (const float*)d_in[7];
    const float* w3    = (const float*)d_in[8];
    const float* b3    = (const float*)d_in[9];
    const float* fhw   = (const float*)d_in[10];
    const float* fhgnw = (const float*)d_in[11];
    const float* fhgnb = (const float*)d_in[12];
    float* out = (float*)d_out;

    const float invN3d = 1.0f / (2.0f*DD*HH*WW);
    const float invN2d = 1.0f / (2.0f*HH*WW);

    k_zero_stats<<<1, 384>>>();                        // launch 1
    k_costvol<<<BATCH*8*HH, 128>>>(fL, fR);            // launch 2
    k_conv3d16<0><<<BATCH*24*16, 128>>>(w1);           // launch 3
    k_norm<<<BATCH*16*24, 256>>>(0, nullptr, gn1w, gn1b, 24, invN3d);  // launch 4
    k_zero_stats<<<1, 384>>>();                        // launch 5 (harmless; aligns ncu -s 5 onto conv2)
    k_conv3d16<1><<<BATCH*24*16, 128>>>(w2);           // launch 6  <-- ncu profiles this
    k_norm<<<BATCH*16*24, 256>>>(1, nullptr, gn2w, gn2b, 24, invN3d);
    k_conv3d_oc1<<<BATCH*24*8, 128>>>(w3, b3);
    k_softmax<<<BATCH*HH, 128>>>(out);
    k_conv2d_feat<<<BATCH*16*2, 128>>>(fL, fhw);
    k_norm<<<BATCH*16, 256>>>(2, out + 196608, fhgnw, fhgnb, 1, invN2d);
}

// round 5
// speedup vs baseline: 1.0460x; 1.0460x over previous
#include <cuda_runtime.h>
#include <math.h>

#define BATCH 8
#define DD 24
#define HH 64
#define WW 128
#define HW (HH*WW)

typedef unsigned long long u64;

// ---------------- packed fp32x2 helpers (Blackwell dual-FP32 pipe) ----------------
__device__ __forceinline__ u64 pk(float lo, float hi) {
    u64 r; asm("mov.b64 %0, {%1,%2};" : "=l"(r) : "f"(lo), "f"(hi)); return r;
}
__device__ __forceinline__ u64 pk1(float v) { return pk(v, v); }
__device__ __forceinline__ void fma2(u64& d, u64 a, u64 b) {
    asm("fma.rn.f32x2 %0, %1, %2, %0;" : "+l"(d) : "l"(a), "l"(b));
}
__device__ __forceinline__ float2 unpk(u64 v) {
    float2 f; asm("mov.b64 {%0,%1}, %2;" : "=f"(f.x), "=f"(f.y) : "l"(v)); return f;
}

// ---------------- scratch (device globals; no allocations allowed) ----------------
__device__ float g_cv[BATCH*8*DD*HH*WW];        // cost volume (B,8,24,64,128)
__device__ float g_x1[BATCH*16*DD*HH*WW];       // conv1 raw
__device__ float g_x1n[BATCH*16*DD*HH*WW];      // conv1 GN+silu
__device__ float g_x2[BATCH*16*DD*HH*WW];       // conv2 raw
__device__ float g_x2n[BATCH*16*DD*HH*WW];      // conv2 GN+silu
__device__ float g_logits[BATCH*DD*HH*WW];      // conv3 output
__device__ float g_feat[BATCH*16*HH*WW];        // feat conv raw
__device__ double g_stats[3*BATCH*8*2];         // [layer][b][group][{sum,sumsq}]

// ---------------- zero stats ----------------
__global__ void k_zero_stats() {
    int i = threadIdx.x;
    if (i < 3*BATCH*8*2) g_stats[i] = 0.0;
}

// ---------------- cost volume ----------------
__global__ void __launch_bounds__(128) k_costvol(const float* __restrict__ fL,
                                                 const float* __restrict__ fR) {
    __shared__ float sR[16*128];
    int x = blockIdx.x;
    int h = x & 63;
    int g = (x >> 6) & 7;
    int b = x >> 9;
    int tid = threadIdx.x;

    const float* baseL = fL + (((size_t)(b*128 + g*16))*HH + h)*WW;
    const float* baseR = fR + (((size_t)(b*128 + g*16))*HH + h)*WW;
    float l[16];
#pragma unroll
    for (int c = 0; c < 16; c++) {
        l[c] = baseL[(size_t)c*HW + tid];
        sR[c*128 + tid] = baseR[(size_t)c*HW + tid];
    }
    __syncthreads();

    float* ov = g_cv + (((size_t)(b*8 + g)*DD)*HH + h)*WW + tid;
    for (int d = 0; d < DD; d++) {
        float s = 0.f;
        if (tid >= d) {
#pragma unroll
            for (int c = 0; c < 16; c++) s += l[c] * sR[c*128 + tid - d];
            s *= 0.0625f;
        }
        ov[(size_t)d*HW] = s;
    }
}

// ---------------- conv3d, 16 oc, fused GN stats, FMA2 (w-pair acc, u64 weights) ----
// grid = B*24*16, block = 128; thread: 8 oc x 8 w (4 w-pairs)
template<int LAYER>
__global__ void __launch_bounds__(128, 3) k_conv3d16(const float* __restrict__ wts) {
    constexpr int CIN = (LAYER == 0) ? 8 : 16;
    constexpr int NPASS = CIN / 8;
    const float* in = (LAYER == 0) ? g_cv : g_x1n;
    float* out = (LAYER == 0) ? g_x1 : g_x2;
    double* stats = g_stats + LAYER*128;

    __shared__ __align__(16) u64 swt[8*27*16];   // duplicated weight pairs, [icl][tap][oc]
    __shared__ float sred[16];
    int tid = threadIdx.x;
    if (tid < 16) sred[tid] = 0.f;

    int x = blockIdx.x;
    int ht = x & 15;
    int d = (x >> 4) % 24;
    int b = x / 384;

    int wt = tid & 15, hr = (tid >> 4) & 3, os = tid >> 6;
    int w0 = wt << 3, h = (ht << 2) + hr, oc0 = os << 3;

    u64 acc[8][4];   // [oc][w-pair]
#pragma unroll
    for (int o = 0; o < 8; o++)
#pragma unroll
        for (int t = 0; t < 4; t++) acc[o][t] = 0ull;

    const float* inb = in + (size_t)b*CIN*DD*HW;

    for (int p = 0; p < NPASS; p++) {
        __syncthreads();
        for (int i = tid; i < 8*27*16; i += 128) {
            int icl = i / 432; int r = i - icl*432; int tap = r >> 4; int oc = r & 15;
            swt[i] = pk1(wts[(oc*CIN + p*8 + icl)*27 + tap]);
        }
        __syncthreads();

        for (int icl = 0; icl < 8; icl++) {
            const float* inc = inb + (size_t)(p*8 + icl)*DD*HW;
#pragma unroll
            for (int kd = 0; kd < 3; kd++) {
                int zd = d + kd - 1;
                if ((unsigned)zd >= (unsigned)DD) continue;
#pragma unroll
                for (int kh = 0; kh < 3; kh++) {
                    int zh = h + kh - 1;
                    if ((unsigned)zh >= (unsigned)HH) continue;
                    const float* row = inc + ((size_t)zd*HH + zh)*WW + w0;
                    float r0 = (w0 == 0) ? 0.f : __ldg(row - 1);
                    float4 va = *(const float4*)row;
                    float4 vb = *(const float4*)(row + 4);
                    float r9 = (w0 == 120) ? 0.f : __ldg(row + 8);
                    // input pairs: pe[t] = (r[2t], r[2t+1]), po[t] = (r[2t+1], r[2t+2])
                    u64 pe[5], po[4];
                    pe[0] = pk(r0, va.x);
                    pe[1] = pk(va.y, va.z);
                    pe[2] = pk(va.w, vb.x);
                    pe[3] = pk(vb.y, vb.z);
                    pe[4] = pk(vb.w, r9);
                    po[0] = pk(va.x, va.y);
                    po[1] = pk(va.z, va.w);
                    po[2] = pk(vb.x, vb.y);
                    po[3] = pk(vb.z, vb.w);
                    int tb = (kd*3 + kh)*3;
                    const u64* wbase = swt + (icl*27 + tb)*16 + oc0;
                    // kw = 0 : pairs pe[0..3] shifted by -1 => uses pe[t] (r[2t], r[2t+1]) with w[kw=0] maps out[2t]+... 
#pragma unroll
                    for (int o = 0; o < 8; o++) {
                        u64 wv0 = wbase[o];
                        fma2(acc[o][0], wv0, pe[0]);
                        fma2(acc[o][1], wv0, pe[1]);
                        fma2(acc[o][2], wv0, pe[2]);
                        fma2(acc[o][3], wv0, pe[3]);
                    }
#pragma unroll
                    for (int o = 0; o < 8; o++) {
                        u64 wv1 = wbase[16 + o];
                        fma2(acc[o][0], wv1, po[0]);
                        fma2(acc[o][1], wv1, po[1]);
                        fma2(acc[o][2], wv1, po[2]);
                        fma2(acc[o][3], wv1, po[3]);
                    }
#pragma unroll
                    for (int o = 0; o < 8; o++) {
                        u64 wv2 = wbase[32 + o];
                        fma2(acc[o][0], wv2, pe[1]);
                        fma2(acc[o][1], wv2, pe[2]);
                        fma2(acc[o][2], wv2, pe[3]);
                        fma2(acc[o][3], wv2, pe[4]);
                    }
                }
            }
        }
    }

    // store + per-group partial stats
    float gs[4], gs2[4];
#pragma unroll
    for (int i = 0; i < 4; i++) { gs[i] = 0.f; gs2[i] = 0.f; }
#pragma unroll
    for (int o = 0; o < 8; o++) {
        float v[8];
#pragma unroll
        for (int t = 0; t < 4; t++) { float2 f = unpk(acc[o][t]); v[2*t] = f.x; v[2*t+1] = f.y; }
        int oc = oc0 + o;
        float* orow = out + ((((size_t)b*16 + oc)*DD + d)*HH + h)*WW + w0;
        *(float4*)orow       = make_float4(v[0], v[1], v[2], v[3]);
        *(float4*)(orow + 4) = make_float4(v[4], v[5], v[6], v[7]);
        float s = 0.f, s2 = 0.f;
#pragma unroll
        for (int j = 0; j < 8; j++) { s += v[j]; s2 += v[j]*v[j]; }
        gs[o >> 1] += s; gs2[o >> 1] += s2;
    }
#pragma unroll
    for (int i = 0; i < 4; i++) {
        int grp = os*4 + i;
        atomicAdd(&sred[grp*2],     gs[i]);
        atomicAdd(&sred[grp*2 + 1], gs2[i]);
    }
    __syncthreads();
    if (tid < 16) atomicAdd(&stats[b*16 + tid], (double)sred[tid]);
}

// ---------------- GN finalize + apply + SiLU ----------------
__global__ void __launch_bounds__(256) k_norm(int which, float* outext,
                                              const float* __restrict__ gw,
                                              const float* __restrict__ gb,
                                              int nslab, float invN) {
    const float* in = (which == 0) ? g_x1 : (which == 1) ? g_x2 : g_feat;
    float* out = (which == 2) ? outext : ((which == 0) ? g_x1n : g_x2n);
    const double* st = g_stats + which*128;

    __shared__ float sA, sB;
    int x = blockIdx.x;
    int s = x % nslab;
    int c = (x / nslab) & 15;
    int b = x / (nslab*16);
    if (threadIdx.x == 0) {
        const double* p = st + ((size_t)b*8 + (c >> 1))*2;
        double mu = p[0] * (double)invN;
        double var = p[1] * (double)invN - mu*mu;
        float rstd = rsqrtf((float)var + 1e-5f);
        float A = rstd * gw[c];
        sA = A;
        sB = gb[c] - (float)mu * A;
    }
    __syncthreads();
    float A = sA, Bv = sB;

    size_t base = ((size_t)(b*16 + c)*nslab + s)*8192;
    const float4* ip = (const float4*)(in + base);
    float4* op = (float4*)(out + base);
    for (int i = threadIdx.x; i < 2048; i += 256) {
        float4 v = ip[i];
        v.x = v.x*A + Bv; v.y = v.y*A + Bv; v.z = v.z*A + Bv; v.w = v.w*A + Bv;
        v.x = v.x / (1.f + __expf(-v.x));
        v.y = v.y / (1.f + __expf(-v.y));
        v.z = v.z / (1.f + __expf(-v.z));
        v.w = v.w / (1.f + __expf(-v.w));
        op[i] = v;
    }
}

// ---------------- conv3d, 1 output channel (logits), FMA2 over w-pairs ----------------
__global__ void __launch_bounds__(128) k_conv3d_oc1(const float* __restrict__ wts,
                                                    const float* __restrict__ bias) {
    __shared__ u64 swt[432];
    int tid = threadIdx.x;
    for (int i = tid; i < 432; i += 128) swt[i] = pk1(wts[i]);
    __syncthreads();

    int x = blockIdx.x;
    int ht = x & 7;
    int d = (x >> 3) % 24;
    int b = x / 192;
    int wt = tid & 15, hr = tid >> 4;
    int w0 = wt << 3, h = ht*8 + hr;

    u64 acc[4];
#pragma unroll
    for (int t = 0; t < 4; t++) acc[t] = 0ull;

    const float* inb = g_x2n + (size_t)b*16*DD*HW;
    for (int ic = 0; ic < 16; ic++) {
        const float* inc = inb + (size_t)ic*DD*HW;
#pragma unroll
        for (int kd = 0; kd < 3; kd++) {
            int zd = d + kd - 1;
            if ((unsigned)zd >= (unsigned)DD) continue;
#pragma unroll
            for (int kh = 0; kh < 3; kh++) {
                int zh = h + kh - 1;
                if ((unsigned)zh >= (unsigned)HH) continue;
                const float* row = inc + ((size_t)zd*HH + zh)*WW + w0;
                float r0 = (w0 == 0) ? 0.f : __ldg(row - 1);
                float4 va = *(const float4*)row;
                float4 vb = *(const float4*)(row + 4);
                float r9 = (w0 == 120) ? 0.f : __ldg(row + 8);
                u64 pe[5], po[4];
                pe[0] = pk(r0, va.x);  pe[1] = pk(va.y, va.z);
                pe[2] = pk(va.w, vb.x); pe[3] = pk(vb.y, vb.z);
                pe[4] = pk(vb.w, r9);
                po[0] = pk(va.x, va.y); po[1] = pk(va.z, va.w);
                po[2] = pk(vb.x, vb.y); po[3] = pk(vb.z, vb.w);
                int tb = (kd*3 + kh)*3;
                u64 wv0 = swt[ic*27 + tb + 0];
                u64 wv1 = swt[ic*27 + tb + 1];
                u64 wv2 = swt[ic*27 + tb + 2];
#pragma unroll
                for (int t = 0; t < 4; t++) {
                    fma2(acc[t], wv0, pe[t]);
                    fma2(acc[t], wv1, po[t]);
                    fma2(acc[t], wv2, pe[t + 1]);
                }
            }
        }
    }
    float bs = bias[0];
    float o[8];
#pragma unroll
    for (int t = 0; t < 4; t++) { float2 f = unpk(acc[t]); o[2*t] = f.x + bs; o[2*t+1] = f.y + bs; }
    float* orow = g_logits + (((size_t)b*DD + d)*HH + h)*WW + w0;
    *(float4*)orow       = make_float4(o[0], o[1], o[2], o[3]);
    *(float4*)(orow + 4) = make_float4(o[4], o[5], o[6], o[7]);
}

// ---------------- softmax over D -> d_out, conf; zero sx, sy ----------------
__global__ void __launch_bounds__(128) k_softmax(float* __restrict__ out) {
    int x = blockIdx.x;
    int h = x & 63;
    int b = x >> 6;
    int w = threadIdx.x;
    const float* lp = g_logits + ((size_t)b*DD*HH + h)*WW + w;
    float l[DD];
    float m = -1e30f;
#pragma unroll
    for (int d = 0; d < DD; d++) { l[d] = lp[(size_t)d*HW]; m = fmaxf(m, l[d]); }
    float S = 0.f, E = 0.f;
#pragma unroll
    for (int d = 0; d < DD; d++) {
        float e = __expf(l[d] - m);
        S += e; E += e * (float)d;
    }
    float inv = 1.f / S;
    int oi = (b*HH + h)*WW + w;
    out[oi]           = E * inv;   // d_out
    out[65536 + oi]   = 0.f;       // sx
    out[131072 + oi]  = 0.f;       // sy
    out[1245184 + oi] = inv;       // conf
}

// ---------------- feature head conv2d (128->16 ch, 3x3) + GN stats, FMA2 ----------------
// grid = B*16*2, block = 128; thread: 4 oc x 8 w (4 w-pairs); weights staged in 4 passes
__global__ void __launch_bounds__(128, 3) k_conv2d_feat(const float* __restrict__ fL,
                                                        const float* __restrict__ wts) {
    __shared__ __align__(16) u64 swt[32*9*16];   // duplicated pairs for 32 input ch
    __shared__ float sred[16];
    int tid = threadIdx.x;
    if (tid < 16) sred[tid] = 0.f;

    int x = blockIdx.x;
    int wtile = x & 1;
    int ht = (x >> 1) & 15;
    int b = x >> 5;

    int wt = tid & 7, os = (tid >> 3) & 3, hr = tid >> 5;
    int w0 = wtile*64 + wt*8;
    int h = ht*4 + hr;
    int oc0 = os*4;

    u64 acc[4][4];   // [oc][w-pair]
#pragma unroll
    for (int o = 0; o < 4; o++)
#pragma unroll
        for (int t = 0; t < 4; t++) acc[o][t] = 0ull;

    for (int p = 0; p < 4; p++) {
        __syncthreads();
        for (int i = tid; i < 32*144; i += 128) {
            int icl = i / 144; int r = i - icl*144; int tap = r >> 4; int oc = r & 15;
            swt[i] = pk1(wts[((size_t)oc*128 + p*32 + icl)*9 + tap]);
        }
        __syncthreads();
        for (int icl = 0; icl < 32; icl++) {
            int ic = p*32 + icl;
            const float* rowb = fL + ((size_t)(b*128 + ic)*HH)*WW;
#pragma unroll
            for (int kh = 0; kh < 3; kh++) {
                int zh = h + kh - 1;
                if ((unsigned)zh >= (unsigned)HH) continue;
                const float* row = rowb + (size_t)zh*WW + w0;
                float r0 = (w0 == 0) ? 0.f : __ldg(row - 1);
                float4 va = *(const float4*)row;
                float4 vb = *(const float4*)(row + 4);
                float r9 = (w0 == 120) ? 0.f : __ldg(row + 8);
                u64 pe[5], po[4];
                pe[0] = pk(r0, va.x);  pe[1] = pk(va.y, va.z);
                pe[2] = pk(va.w, vb.x); pe[3] = pk(vb.y, vb.z);
                pe[4] = pk(vb.w, r9);
                po[0] = pk(va.x, va.y); po[1] = pk(va.z, va.w);
                po[2] = pk(vb.x, vb.y); po[3] = pk(vb.z, vb.w);
                const u64* wbase = swt + (icl*9 + kh*3)*16 + oc0;
#pragma unroll
                for (int o = 0; o < 4; o++) {
                    u64 wv0 = wbase[o];
                    fma2(acc[o][0], wv0, pe[0]);
                    fma2(acc[o][1], wv0, pe[1]);
                    fma2(acc[o][2], wv0, pe[2]);
                    fma2(acc[o][3], wv0, pe[3]);
                }
#pragma unroll
                for (int o = 0; o < 4; o++) {
                    u64 wv1 = wbase[16 + o];
                    fma2(acc[o][0], wv1, po[0]);
                    fma2(acc[o][1], wv1, po[1]);
                    fma2(acc[o][2], wv1, po[2]);
                    fma2(acc[o][3], wv1, po[3]);
                }
#pragma unroll
                for (int o = 0; o < 4; o++) {
                    u64 wv2 = wbase[32 + o];
                    fma2(acc[o][0], wv2, pe[1]);
                    fma2(acc[o][1], wv2, pe[2]);
                    fma2(acc[o][2], wv2, pe[3]);
                    fma2(acc[o][3], wv2, pe[4]);
                }
            }
        }
    }

    // store + stats (layer 2)
    float gs[2], gs2[2];
    gs[0] = gs[1] = gs2[0] = gs2[1] = 0.f;
#pragma unroll
    for (int o = 0; o < 4; o++) {
        float v[8];
#pragma unroll
        for (int t = 0; t < 4; t++) { float2 f = unpk(acc[o][t]); v[2*t] = f.x; v[2*t+1] = f.y; }
        int oc = oc0 + o;
        float* orow = g_feat + (((size_t)b*16 + oc)*HH + h)*WW + w0;
        *(float4*)orow       = make_float4(v[0], v[1], v[2], v[3]);
        *(float4*)(orow + 4) = make_float4(v[4], v[5], v[6], v[7]);
        float s = 0.f, s2 = 0.f;
#pragma unroll
        for (int j = 0; j < 8; j++) { s += v[j]; s2 += v[j]*v[j]; }
        gs[o >> 1] += s; gs2[o >> 1] += s2;
    }
#pragma unroll
    for (int i = 0; i < 2; i++) {
        int grp = os*2 + i;
        atomicAdd(&sred[grp*2],     gs[i]);
        atomicAdd(&sred[grp*2 + 1], gs2[i]);
    }
    __syncthreads();
    if (tid < 16) atomicAdd(&g_stats[2*128 + b*16 + tid], (double)sred[tid]);
}

// ---------------- launch ----------------
extern "C" void kernel_launch(void* const* d_in, const int* in_sizes, int n_in,
                              void* d_out, int out_size) {
    const float* fL    = (const float*)d_in[0];
    const float* fR    = (const float*)d_in[1];
    const float* w1    = (const float*)d_in[2];
    const float* gn1w  = (const float*)d_in[3];
    const float* gn1b  = (const float*)d_in[4];
    const float* w2    = (const float*)d_in[5];
    const float* gn2w  = (const float*)d_in[6];
    const float* gn2b  = (const float*)d_in[7];
    const float* w3    = (const float*)d_in[8];
    const float* b3    = (const float*)d_in[9];
    const float* fhw   = (const float*)d_in[10];
    const float* fhgnw = (const float*)d_in[11];
    const float* fhgnb = (const float*)d_in[12];
    float* out = (float*)d_out;

    const float invN3d = 1.0f / (2.0f*DD*HH*WW);
    const float invN2d = 1.0f / (2.0f*HH*WW);

    k_zero_stats<<<1, 384>>>();                        // launch 1
    k_costvol<<<BATCH*8*HH, 128>>>(fL, fR);            // launch 2
    k_conv3d16<0><<<BATCH*24*16, 128>>>(w1);           // launch 3
    k_norm<<<BATCH*16*24, 256>>>(0, nullptr, gn1w, gn1b, 24, invN3d);  // launch 4
    k_zero_stats<<<1, 384>>>();                        // launch 5 (harmless; aligns ncu -s 5 onto conv2)
    k_conv3d16<1><<<BATCH*24*16, 128>>>(w2);           // launch 6  <-- ncu profiles this
    k_norm<<<BATCH*16*24, 256>>>(1, nullptr, gn2w, gn2b, 24, invN3d);
    k_conv3d_oc1<<<BATCH*24*8, 128>>>(w3, b3);
    k_softmax<<<BATCH*HH, 128>>>(out);
    k_conv2d_feat<<<BATCH*16*2, 128>>>(fL, fhw);
    k_norm<<<BATCH*16, 256>>>(2, out + 196608, fhgnw, fhgnb, 1, invN2d);
}

// round 6
// speedup vs baseline: 1.1599x; 1.1089x over previous
#include <cuda_runtime.h>
#include <cuda_bf16.h>
#include <math.h>

#define BATCH 8
#define DD 24
#define HH 64
#define WW 128
#define HW (HH*WW)

typedef unsigned long long u64;
typedef unsigned int u32;

// ---------------- packed fp32x2 helpers ----------------
__device__ __forceinline__ u64 pk(float lo, float hi) {
    u64 r; asm("mov.b64 %0, {%1,%2};" : "=l"(r) : "f"(lo), "f"(hi)); return r;
}
__device__ __forceinline__ u64 pk1(float v) { return pk(v, v); }
__device__ __forceinline__ void fma2(u64& d, u64 a, u64 b) {
    asm("fma.rn.f32x2 %0, %1, %2, %0;" : "+l"(d) : "l"(a), "l"(b));
}
__device__ __forceinline__ float2 unpk(u64 v) {
    float2 f; asm("mov.b64 {%0,%1}, %2;" : "=f"(f.x), "=f"(f.y) : "l"(v)); return f;
}

// ---------------- mma / ldmatrix helpers ----------------
__device__ __forceinline__ u32 smem_u32(const void* p) {
    u32 a; asm("{ .reg .u64 t; cvta.to.shared.u64 t, %1; cvt.u32.u64 %0, t; }" : "=r"(a) : "l"(p));
    return a;
}
__device__ __forceinline__ void ldsm4(u32 a, u32& r0, u32& r1, u32& r2, u32& r3) {
    asm volatile("ldmatrix.sync.aligned.m8n8.x4.shared.b16 {%0,%1,%2,%3}, [%4];"
                 : "=r"(r0), "=r"(r1), "=r"(r2), "=r"(r3) : "r"(a));
}
__device__ __forceinline__ void ldsm2(u32 a, u32& r0, u32& r1) {
    asm volatile("ldmatrix.sync.aligned.m8n8.x2.shared.b16 {%0,%1}, [%2];"
                 : "=r"(r0), "=r"(r1) : "r"(a));
}
__device__ __forceinline__ void mma16816(float* d, u32 a0, u32 a1, u32 a2, u32 a3, u32 b0, u32 b1) {
    asm volatile("mma.sync.aligned.m16n8k16.row.col.f32.bf16.bf16.f32 "
                 "{%0,%1,%2,%3}, {%4,%5,%6,%7}, {%8,%9}, {%0,%1,%2,%3};"
                 : "+f"(d[0]), "+f"(d[1]), "+f"(d[2]), "+f"(d[3])
                 : "r"(a0), "r"(a1), "r"(a2), "r"(a3), "r"(b0), "r"(b1));
}

// ---------------- scratch ----------------
__device__ float g_cv[BATCH*8*DD*HH*WW];
__device__ float g_x1[BATCH*16*DD*HH*WW];
__device__ float g_x1n[BATCH*16*DD*HH*WW];
__device__ float g_x2[BATCH*16*DD*HH*WW];
__device__ float g_x2n[BATCH*16*DD*HH*WW];
__device__ float g_logits[BATCH*DD*HH*WW];
__device__ float g_feat[BATCH*16*HH*WW];
__device__ double g_stats[3*BATCH*8*2];

__global__ void k_zero_stats() {
    int i = threadIdx.x;
    if (i < 3*BATCH*8*2) g_stats[i] = 0.0;
}

// ---------------- cost volume (unchanged, proven) ----------------
__global__ void __launch_bounds__(128) k_costvol(const float* __restrict__ fL,
                                                 const float* __restrict__ fR) {
    __shared__ float sR[16*128];
    int x = blockIdx.x;
    int h = x & 63, g = (x >> 6) & 7, b = x >> 9;
    int tid = threadIdx.x;
    const float* baseL = fL + (((size_t)(b*128 + g*16))*HH + h)*WW;
    const float* baseR = fR + (((size_t)(b*128 + g*16))*HH + h)*WW;
    float l[16];
#pragma unroll
    for (int c = 0; c < 16; c++) {
        l[c] = baseL[(size_t)c*HW + tid];
        sR[c*128 + tid] = baseR[(size_t)c*HW + tid];
    }
    __syncthreads();
    float* ov = g_cv + (((size_t)(b*8 + g)*DD)*HH + h)*WW + tid;
    for (int d = 0; d < DD; d++) {
        float s = 0.f;
        if (tid >= d) {
#pragma unroll
            for (int c = 0; c < 16; c++) s += l[c] * sR[c*128 + tid - d];
            s *= 0.0625f;
        }
        ov[(size_t)d*HW] = s;
    }
}

// ================= tensor-core conv3d (16 oc), bf16 split, fused GN stats =========
// grid = B*32*4 (b, h-pair, d-sixth), block = 256 (8 warps)
// warp: hl = wrp>>2 (h row), wq = wrp&3 (32-w slice); 2 pixel tiles of 16
#define PLANE_B (520*64)
#define CONV_SMEM (3*PLANE_B + 2*27*16*16*2)

template<int CIN>
__global__ void __launch_bounds__(256) k_conv_tc(const float* __restrict__ wts) {
    const float* in = (CIN == 8) ? g_cv : g_x1n;
    float* out = (CIN == 8) ? g_x1 : g_x2;
    double* stats = g_stats + ((CIN == 8) ? 0 : 1)*128;

    extern __shared__ char smem[];
    char* a_sm = smem;
    __nv_bfloat16* w_sm = (__nv_bfloat16*)(smem + 3*PLANE_B);
    __shared__ float sred[16];

    u32 a_base = smem_u32(a_sm);
    u32 w_base = smem_u32(w_sm);
    int tid = threadIdx.x, lane = tid & 31, wrp = tid >> 5;
    int hl = wrp >> 2, wq = wrp & 3, w0 = wq*32;
    if (tid < 16) sred[tid] = 0.f;

    int x = blockIdx.x;
    int dq = x & 3, hp = (x >> 2) & 31, b = x >> 7;
    int d0 = dq*6, h0 = hp*2;

    // stage weights: [split][tap][oc][ic] bf16 (hi then lo)
    for (int i = tid; i < 27*256; i += 256) {
        int ic = i & 15, oc = (i >> 4) & 15, tap = i >> 8;
        float v = (ic < CIN) ? wts[(oc*CIN + ic)*27 + tap] : 0.f;
        __nv_bfloat16 hi = __float2bfloat16(v);
        __nv_bfloat16 lo = __float2bfloat16(v - __bfloat162float(hi));
        w_sm[i] = hi; w_sm[27*256 + i] = lo;
    }

    // stage one input zd-plane into ring slot (rows: [zhl 0..3][col 0..129],
    // col = w+1; 64B row = 4x16B chunks [hi c0-7][hi c8-15][lo c0-7][lo c8-15],
    // chunk index XOR-swizzled by (row&3))
    auto stage = [&](int zd, int slot) {
        char* pl = a_sm + slot*PLANE_B;
        if ((unsigned)zd >= 24u) {
            for (int i = tid; i < 520*16; i += 256) ((u32*)pl)[i] = 0u;
            return;
        }
        for (int it = tid; it < 8192; it += 256) {
            int w = it & 127; int q = it >> 7;
            int c = q & 15, zhl = q >> 4;
            int zh = h0 - 1 + zhl;
            float v = 0.f;
            if ((unsigned)zh < 64u && c < CIN)
                v = in[((size_t)(b*CIN + c)*DD + zd)*HW + zh*WW + w];
            __nv_bfloat16 hi = __float2bfloat16(v);
            __nv_bfloat16 lo = __float2bfloat16(v - __bfloat162float(hi));
            int r = zhl*130 + w + 1;
            int ch = c >> 3;
            char* rowb = pl + r*64;
            *(__nv_bfloat16*)(rowb + ((ch ^ (r & 3))*16) + (c & 7)*2) = hi;
            *(__nv_bfloat16*)(rowb + (((2 | ch) ^ (r & 3))*16) + (c & 7)*2) = lo;
        }
        // re-zero halo columns (col 0 and 129) — bounce buffer may have dirtied them
        for (int i = tid; i < 8*16; i += 256) {
            int u = i & 15, rr = i >> 4;
            int zhl = rr >> 1, col = (rr & 1)*129;
            ((u32*)(pl + (zhl*130 + col)*64))[u] = 0u;
        }
    };

    stage(d0 - 1, (d0) % 3);
    stage(d0,     (d0 + 1) % 3);

    float acc[2][2][4];
    float gsum[2] = {0.f, 0.f}, gss[2] = {0.f, 0.f};

    for (int d = d0; d < d0 + 6; d++) {
        __syncthreads();
        stage(d + 1, (d + 2) % 3);
        __syncthreads();

#pragma unroll
        for (int t = 0; t < 2; t++)
#pragma unroll
            for (int oh = 0; oh < 2; oh++)
#pragma unroll
                for (int r = 0; r < 4; r++) acc[t][oh][r] = 0.f;

        for (int kd = 0; kd < 3; kd++) {
            u32 pbase = a_base + ((d + kd) % 3)*PLANE_B;
#pragma unroll
            for (int kh = 0; kh < 3; kh++) {
                int zhl = hl + kh;
                u32 bf[3][2][2][2];
#pragma unroll
                for (int kw = 0; kw < 3; kw++) {
                    int tap = (kd*3 + kh)*3 + kw;
#pragma unroll
                    for (int sp = 0; sp < 2; sp++)
#pragma unroll
                        for (int oh = 0; oh < 2; oh++) {
                            u32 ba = w_base + ((sp*27 + tap)*256 + (oh*8 + (lane & 7))*16
                                               + ((lane >> 3) & 1)*8)*2;
                            ldsm2(ba, bf[kw][sp][oh][0], bf[kw][sp][oh][1]);
                        }
                }
#pragma unroll
                for (int tile = 0; tile < 2; tile++) {
                    int colb = w0 + tile*16;
#pragma unroll
                    for (int kw = 0; kw < 3; kw++) {
                        int r = zhl*130 + colb + kw + (lane & 15);
                        u32 ah = pbase + (u32)r*64 + (((lane >> 4) ^ (r & 3))*16);
                        u32 al = pbase + (u32)r*64 + ((((lane >> 4) | 2) ^ (r & 3))*16);
                        u32 h0r, h1r, h2r, h3r, l0r, l1r, l2r, l3r;
                        ldsm4(ah, h0r, h1r, h2r, h3r);
                        ldsm4(al, l0r, l1r, l2r, l3r);
#pragma unroll
                        for (int oh = 0; oh < 2; oh++) {
                            mma16816(acc[tile][oh], h0r, h1r, h2r, h3r,
                                     bf[kw][0][oh][0], bf[kw][0][oh][1]);
                            mma16816(acc[tile][oh], h0r, h1r, h2r, h3r,
                                     bf[kw][1][oh][0], bf[kw][1][oh][1]);
                            mma16816(acc[tile][oh], l0r, l1r, l2r, l3r,
                                     bf[kw][0][oh][0], bf[kw][0][oh][1]);
                        }
                    }
                }
            }
        }

        // stats
#pragma unroll
        for (int oh = 0; oh < 2; oh++) {
            float s = 0.f, s2 = 0.f;
#pragma unroll
            for (int t = 0; t < 2; t++)
#pragma unroll
                for (int r = 0; r < 4; r++) { float v = acc[t][oh][r]; s += v; s2 += v*v; }
            gsum[oh] += s; gss[oh] += s2;
        }

        // bounce into retiring ring slot, then coalesced store
        __syncthreads();
        float* bounce = (float*)(a_sm + ((d) % 3)*PLANE_B);
#pragma unroll
        for (int t = 0; t < 2; t++)
#pragma unroll
            for (int oh = 0; oh < 2; oh++)
#pragma unroll
                for (int r = 0; r < 4; r++) {
                    int oc = oh*8 + (lane & 3)*2 + (r & 1);
                    int px = w0 + t*16 + (lane >> 2) + ((r >> 1)*8);
                    bounce[oc*260 + hl*128 + px] = acc[t][oh][r];
                }
        __syncthreads();
        float* ob = out + ((size_t)b*16*DD + d)*HW;
        for (int i = tid; i < 1024; i += 256) {
            int oc = i >> 6, rem = i & 63;
            int h2 = rem >> 5, w4 = rem & 31;
            float4 v = *(float4*)&bounce[oc*260 + h2*128 + w4*4];
            *(float4*)&ob[(size_t)oc*DD*HW + (h0 + h2)*WW + w4*4] = v;
        }
    }

    int g0 = lane & 3;
    atomicAdd(&sred[g0*2],       gsum[0]); atomicAdd(&sred[g0*2 + 1],       gss[0]);
    atomicAdd(&sred[(4+g0)*2],   gsum[1]); atomicAdd(&sred[(4+g0)*2 + 1],   gss[1]);
    __syncthreads();
    if (tid < 16) atomicAdd(&stats[b*16 + tid], (double)sred[tid]);
}

// ---------------- GN finalize + apply + SiLU (unchanged) ----------------
__global__ void __launch_bounds__(256) k_norm(int which, float* outext,
                                              const float* __restrict__ gw,
                                              const float* __restrict__ gb,
                                              int nslab, float invN) {
    const float* in = (which == 0) ? g_x1 : (which == 1) ? g_x2 : g_feat;
    float* out = (which == 2) ? outext : ((which == 0) ? g_x1n : g_x2n);
    const double* st = g_stats + which*128;
    __shared__ float sA, sB;
    int x = blockIdx.x;
    int s = x % nslab, c = (x / nslab) & 15, b = x / (nslab*16);
    if (threadIdx.x == 0) {
        const double* p = st + ((size_t)b*8 + (c >> 1))*2;
        double mu = p[0] * (double)invN;
        double var = p[1] * (double)invN - mu*mu;
        float rstd = rsqrtf((float)var + 1e-5f);
        float A = rstd * gw[c];
        sA = A; sB = gb[c] - (float)mu * A;
    }
    __syncthreads();
    float A = sA, Bv = sB;
    size_t base = ((size_t)(b*16 + c)*nslab + s)*8192;
    const float4* ip = (const float4*)(in + base);
    float4* op = (float4*)(out + base);
    for (int i = threadIdx.x; i < 2048; i += 256) {
        float4 v = ip[i];
        v.x = v.x*A + Bv; v.y = v.y*A + Bv; v.z = v.z*A + Bv; v.w = v.w*A + Bv;
        v.x = v.x / (1.f + __expf(-v.x));
        v.y = v.y / (1.f + __expf(-v.y));
        v.z = v.z / (1.f + __expf(-v.z));
        v.w = v.w / (1.f + __expf(-v.w));
        op[i] = v;
    }
}

// ---------------- conv3d oc=1 (FMA2, unchanged) ----------------
__global__ void __launch_bounds__(128) k_conv3d_oc1(const float* __restrict__ wts,
                                                    const float* __restrict__ bias) {
    __shared__ u64 swt[432];
    int tid = threadIdx.x;
    for (int i = tid; i < 432; i += 128) swt[i] = pk1(wts[i]);
    __syncthreads();
    int x = blockIdx.x;
    int ht = x & 7, d = (x >> 3) % 24, b = x / 192;
    int wt = tid & 15, hr = tid >> 4;
    int w0 = wt << 3, h = ht*8 + hr;
    u64 acc[4];
#pragma unroll
    for (int t = 0; t < 4; t++) acc[t] = 0ull;
    const float* inb = g_x2n + (size_t)b*16*DD*HW;
    for (int ic = 0; ic < 16; ic++) {
        const float* inc = inb + (size_t)ic*DD*HW;
#pragma unroll
        for (int kd = 0; kd < 3; kd++) {
            int zd = d + kd - 1;
            if ((unsigned)zd >= (unsigned)DD) continue;
#pragma unroll
            for (int kh = 0; kh < 3; kh++) {
                int zh = h + kh - 1;
                if ((unsigned)zh >= (unsigned)HH) continue;
                const float* row = inc + ((size_t)zd*HH + zh)*WW + w0;
                float r0 = (w0 == 0) ? 0.f : __ldg(row - 1);
                float4 va = *(const float4*)row;
                float4 vb = *(const float4*)(row + 4);
                float r9 = (w0 == 120) ? 0.f : __ldg(row + 8);
                u64 pe[5], po[4];
                pe[0] = pk(r0, va.x);  pe[1] = pk(va.y, va.z);
                pe[2] = pk(va.w, vb.x); pe[3] = pk(vb.y, vb.z);
                pe[4] = pk(vb.w, r9);
                po[0] = pk(va.x, va.y); po[1] = pk(va.z, va.w);
                po[2] = pk(vb.x, vb.y); po[3] = pk(vb.z, vb.w);
                int tb = (kd*3 + kh)*3;
                u64 wv0 = swt[ic*27 + tb + 0];
                u64 wv1 = swt[ic*27 + tb + 1];
                u64 wv2 = swt[ic*27 + tb + 2];
#pragma unroll
                for (int t = 0; t < 4; t++) {
                    fma2(acc[t], wv0, pe[t]);
                    fma2(acc[t], wv1, po[t]);
                    fma2(acc[t], wv2, pe[t + 1]);
                }
            }
        }
    }
    float bs = bias[0];
    float o[8];
#pragma unroll
    for (int t = 0; t < 4; t++) { float2 f = unpk(acc[t]); o[2*t] = f.x + bs; o[2*t+1] = f.y + bs; }
    float* orow = g_logits + (((size_t)b*DD + d)*HH + h)*WW + w0;
    *(float4*)orow       = make_float4(o[0], o[1], o[2], o[3]);
    *(float4*)(orow + 4) = make_float4(o[4], o[5], o[6], o[7]);
}

// ---------------- softmax (unchanged) ----------------
__global__ void __launch_bounds__(128) k_softmax(float* __restrict__ out) {
    int x = blockIdx.x;
    int h = x & 63, b = x >> 6;
    int w = threadIdx.x;
    const float* lp = g_logits + ((size_t)b*DD*HH + h)*WW + w;
    float l[DD];
    float m = -1e30f;
#pragma unroll
    for (int d = 0; d < DD; d++) { l[d] = lp[(size_t)d*HW]; m = fmaxf(m, l[d]); }
    float S = 0.f, E = 0.f;
#pragma unroll
    for (int d = 0; d < DD; d++) {
        float e = __expf(l[d] - m);
        S += e; E += e * (float)d;
    }
    float inv = 1.f / S;
    int oi = (b*HH + h)*WW + w;
    out[oi]           = E * inv;
    out[65536 + oi]   = 0.f;
    out[131072 + oi]  = 0.f;
    out[1245184 + oi] = inv;
}

// ---------------- feature head conv2d (FMA2, unchanged from R2) ----------------
__global__ void __launch_bounds__(128, 3) k_conv2d_feat(const float* __restrict__ fL,
                                                        const float* __restrict__ wts) {
    __shared__ __align__(16) u64 swt[32*9*16];
    __shared__ float sred[16];
    int tid = threadIdx.x;
    if (tid < 16) sred[tid] = 0.f;
    int x = blockIdx.x;
    int wtile = x & 1, ht = (x >> 1) & 15, b = x >> 5;
    int wt = tid & 7, os = (tid >> 3) & 3, hr = tid >> 5;
    int w0 = wtile*64 + wt*8, h = ht*4 + hr, oc0 = os*4;
    u64 acc[4][4];
#pragma unroll
    for (int o = 0; o < 4; o++)
#pragma unroll
        for (int t = 0; t < 4; t++) acc[o][t] = 0ull;
    for (int p = 0; p < 4; p++) {
        __syncthreads();
        for (int i = tid; i < 32*144; i += 128) {
            int icl = i / 144; int r = i - icl*144; int tap = r >> 4; int oc = r & 15;
            swt[i] = pk1(wts[((size_t)oc*128 + p*32 + icl)*9 + tap]);
        }
        __syncthreads();
        for (int icl = 0; icl < 32; icl++) {
            int ic = p*32 + icl;
            const float* rowb = fL + ((size_t)(b*128 + ic)*HH)*WW;
#pragma unroll
            for (int kh = 0; kh < 3; kh++) {
                int zh = h + kh - 1;
                if ((unsigned)zh >= (unsigned)HH) continue;
                const float* row = rowb + (size_t)zh*WW + w0;
                float r0 = (w0 == 0) ? 0.f : __ldg(row - 1);
                float4 va = *(const float4*)row;
                float4 vb = *(const float4*)(row + 4);
                float r9 = (w0 == 120) ? 0.f : __ldg(row + 8);
                u64 pe[5], po[4];
                pe[0] = pk(r0, va.x);  pe[1] = pk(va.y, va.z);
                pe[2] = pk(va.w, vb.x); pe[3] = pk(vb.y, vb.z);
                pe[4] = pk(vb.w, r9);
                po[0] = pk(va.x, va.y); po[1] = pk(va.z, va.w);
                po[2] = pk(vb.x, vb.y); po[3] = pk(vb.z, vb.w);
                const u64* wbase = swt + (icl*9 + kh*3)*16 + oc0;
#pragma unroll
                for (int o = 0; o < 4; o++) {
                    u64 wv0 = wbase[o];
                    fma2(acc[o][0], wv0, pe[0]); fma2(acc[o][1], wv0, pe[1]);
                    fma2(acc[o][2], wv0, pe[2]); fma2(acc[o][3], wv0, pe[3]);
                }
#pragma unroll
                for (int o = 0; o < 4; o++) {
                    u64 wv1 = wbase[16 + o];
                    fma2(acc[o][0], wv1, po[0]); fma2(acc[o][1], wv1, po[1]);
                    fma2(acc[o][2], wv1, po[2]); fma2(acc[o][3], wv1, po[3]);
                }
#pragma unroll
                for (int o = 0; o < 4; o++) {
                    u64 wv2 = wbase[32 + o];
                    fma2(acc[o][0], wv2, pe[1]); fma2(acc[o][1], wv2, pe[2]);
                    fma2(acc[o][2], wv2, pe[3]); fma2(acc[o][3], wv2, pe[4]);
                }
            }
        }
    }
    float gs[2], gs2[2];
    gs[0] = gs[1] = gs2[0] = gs2[1] = 0.f;
#pragma unroll
    for (int o = 0; o < 4; o++) {
        float v[8];
#pragma unroll
        for (int t = 0; t < 4; t++) { float2 f = unpk(acc[o][t]); v[2*t] = f.x; v[2*t+1] = f.y; }
        int oc = oc0 + o;
        float* orow = g_feat + (((size_t)b*16 + oc)*HH + h)*WW + w0;
        *(float4*)orow       = make_float4(v[0], v[1], v[2], v[3]);
        *(float4*)(orow + 4) = make_float4(v[4], v[5], v[6], v[7]);
        float s = 0.f, s2 = 0.f;
#pragma unroll
        for (int j = 0; j < 8; j++) { s += v[j]; s2 += v[j]*v[j]; }
        gs[o >> 1] += s; gs2[o >> 1] += s2;
    }
#pragma unroll
    for (int i = 0; i < 2; i++) {
        int grp = os*2 + i;
        atomicAdd(&sred[grp*2],     gs[i]);
        atomicAdd(&sred[grp*2 + 1], gs2[i]);
    }
    __syncthreads();
    if (tid < 16) atomicAdd(&g_stats[2*128 + b*16 + tid], (double)sred[tid]);
}

// ---------------- launch ----------------
extern "C" void kernel_launch(void* const* d_in, const int* in_sizes, int n_in,
                              void* d_out, int out_size) {
    const float* fL    = (const float*)d_in[0];
    const float* fR    = (const float*)d_in[1];
    const float* w1    = (const float*)d_in[2];
    const float* gn1w  = (const float*)d_in[3];
    const float* gn1b  = (const float*)d_in[4];
    const float* w2    = (const float*)d_in[5];
    const float* gn2w  = (const float*)d_in[6];
    const float* gn2b  = (const float*)d_in[7];
    const float* w3    = (const float*)d_in[8];
    const float* b3    = (const float*)d_in[9];
    const float* fhw   = (const float*)d_in[10];
    const float* fhgnw = (const float*)d_in[11];
    const float* fhgnb = (const float*)d_in[12];
    float* out = (float*)d_out;

    const float invN3d = 1.0f / (2.0f*DD*HH*WW);
    const float invN2d = 1.0f / (2.0f*HH*WW);

    cudaFuncSetAttribute(k_conv_tc<8>,  cudaFuncAttributeMaxDynamicSharedMemorySize, CONV_SMEM);
    cudaFuncSetAttribute(k_conv_tc<16>, cudaFuncAttributeMaxDynamicSharedMemorySize, CONV_SMEM);

    k_zero_stats<<<1, 384>>>();
    k_costvol<<<BATCH*8*HH, 128>>>(fL, fR);
    k_conv_tc<8><<<1024, 256, CONV_SMEM>>>(w1);
    k_norm<<<BATCH*16*24, 256>>>(0, nullptr, gn1w, gn1b, 24, invN3d);
    k_conv_tc<16><<<1024, 256, CONV_SMEM>>>(w2);
    k_norm<<<BATCH*16*24, 256>>>(1, nullptr, gn2w, gn2b, 24, invN3d);
    k_conv3d_oc1<<<BATCH*24*8, 128>>>(w3, b3);
    k_softmax<<<BATCH*HH, 128>>>(out);
    k_conv2d_feat<<<BATCH*16*2, 128>>>(fL, fhw);
    k_norm<<<BATCH*16, 256>>>(2, out + 196608, fhgnw, fhgnb, 1, invN2d);
}